// round 5
// baseline (speedup 1.0000x reference)
#include <cuda_runtime.h>

namespace {

using u64 = unsigned long long;

constexpr int B  = 4096;
constexpr int T  = 1000;
constexpr int IN = 3;

constexpr int WARPS = 10;           // warps per block -> 320 threads, 1 block/SM
constexpr int EPW   = 3;            // elements per warp (30 active lanes)
constexpr int EPB   = WARPS * EPW;  // 30 elements per block
constexpr int NBLK  = (B + EPB - 1) / EPB;  // 137 blocks <= 148 SMs: ONE wave
constexpr int RS    = 12;           // padded row stride (floats), 48B (16B-aligned rows)

// ---- packed f32x2 helpers ----
__device__ __forceinline__ u64 fma2(u64 a, u64 b, u64 c) {
    u64 d;
    asm("fma.rn.f32x2 %0, %1, %2, %3;" : "=l"(d) : "l"(a), "l"(b), "l"(c));
    return d;
}
__device__ __forceinline__ u64 pack2(float lo, float hi) {
    u64 d;
    asm("mov.b64 %0, {%1, %2};" : "=l"(d) : "f"(lo), "f"(hi));
    return d;
}
__device__ __forceinline__ float hsum2b(u64 v, float b) {
    float lo, hi;
    asm("mov.b64 {%0, %1}, %2;" : "=f"(lo), "=f"(hi) : "l"(v));
    return (lo + hi) + b;
}

// MUFU.TANH — single-SFU activation
__device__ __forceinline__ float tanhapx(float v) {
    float y;
    asm("tanh.approx.f32 %0, %1;" : "=f"(y) : "f"(v));
    return y;
}
// sigmoid(x) where a = x/2 already (0.5 folded into weights/biases at init)
__device__ __forceinline__ float sighalf(float a) {
    return fmaf(0.5f, tanhapx(a), 0.5f);
}

// Load a 10-float smem row (16B-aligned, RS=12 padding) as 5 packed f32x2 values.
__device__ __forceinline__ void load10p(const float* __restrict__ p, u64* v) {
    ulonglong2 a = *reinterpret_cast<const ulonglong2*>(p);
    ulonglong2 b = *reinterpret_cast<const ulonglong2*>(p + 4);
    v[0] = a.x; v[1] = a.y; v[2] = b.x; v[3] = b.y;
    v[4] = *reinterpret_cast<const u64*>(p + 8);
}

// GRU cell, weights as packed register arrays. r/z rows pre-scaled by 0.5.
__device__ __forceinline__ float cell_reg(
    const u64 (&wi)[3][5], const u64 (&wh)[3][5],
    float bR, float bZ, float bXN, float bHN,
    const u64* __restrict__ iv, const u64* __restrict__ hv, float h)
{
    u64 aR = 0ull, aZ = 0ull, aN = 0ull, aH = 0ull;
#pragma unroll
    for (int k = 0; k < 5; k++) {
        aR = fma2(wi[0][k], iv[k], aR);
        aZ = fma2(wi[1][k], iv[k], aZ);
        aN = fma2(wi[2][k], iv[k], aN);
    }
#pragma unroll
    for (int k = 0; k < 5; k++) {
        aR = fma2(wh[0][k], hv[k], aR);
        aZ = fma2(wh[1][k], hv[k], aZ);
        aH = fma2(wh[2][k], hv[k], aH);
    }
    float r = sighalf(hsum2b(aR, bR));
    float z = sighalf(hsum2b(aZ, bZ));
    float n = tanhapx(fmaf(r, hsum2b(aH, bHN), hsum2b(aN, bXN)));
    return n + z * (h - n);
}

__global__ void __launch_bounds__(WARPS * 32, 1)
gru3_fused(const float* __restrict__ x,
           const float* __restrict__ Wih0, const float* __restrict__ Whh0,
           const float* __restrict__ bih0, const float* __restrict__ bhh0,
           const float* __restrict__ Wih1, const float* __restrict__ Whh1,
           const float* __restrict__ bih1, const float* __restrict__ bhh1,
           const float* __restrict__ Wih2, const float* __restrict__ Whh2,
           const float* __restrict__ bih2, const float* __restrict__ bhh2,
           const float* __restrict__ Wout, const float* __restrict__ bout,
           float* __restrict__ out)
{
    __shared__ __align__(16) float s_h[2][3][EPB][RS];   // [pingpong][layer][elem][unit]

    const int tid  = threadIdx.x;
    const int lane = tid & 31;
    const int warp = tid >> 5;
    const int g    = lane / 10;        // element slot within warp
    const int j    = lane - g * 10;    // hidden unit
    const int eb   = warp * EPW + g;
    const int e    = blockIdx.x * EPB + eb;
    const bool act = (lane < 30) && (e < B);

    for (int idx = tid; idx < 2 * 3 * EPB * RS; idx += WARPS * 32)
        (&s_h[0][0][0][0])[idx] = 0.0f;

    // ---- ALL weights in registers (r/z rows pre-scaled by 0.5 for folded sigmoid) ----
    float w0x[3][3];
    u64 w0h[3][5], w1i[3][5], w1h[3][5], w2i[3][5], w2h[3][5];
#pragma unroll
    for (int gg = 0; gg < 3; gg++) {
        const int row = gg * 10 + j;
        const float s = (gg < 2) ? 0.5f : 1.0f;
#pragma unroll
        for (int k = 0; k < 3; k++) w0x[gg][k] = Wih0[row * 3 + k] * s;
#pragma unroll
        for (int k = 0; k < 5; k++) {
            w0h[gg][k] = pack2(Whh0[row * 10 + 2 * k] * s, Whh0[row * 10 + 2 * k + 1] * s);
            w1i[gg][k] = pack2(Wih1[row * 10 + 2 * k] * s, Wih1[row * 10 + 2 * k + 1] * s);
            w1h[gg][k] = pack2(Whh1[row * 10 + 2 * k] * s, Whh1[row * 10 + 2 * k + 1] * s);
            w2i[gg][k] = pack2(Wih2[row * 10 + 2 * k] * s, Wih2[row * 10 + 2 * k + 1] * s);
            w2h[gg][k] = pack2(Whh2[row * 10 + 2 * k] * s, Whh2[row * 10 + 2 * k + 1] * s);
        }
    }
    // Scalar biases (r/z halved to match folded sigmoid pre-scale).
    const float b0R  = 0.5f * (bih0[j] + bhh0[j]);
    const float b0Z  = 0.5f * (bih0[10 + j] + bhh0[10 + j]);
    const float b0XN = bih0[20 + j];
    const float b0HN = bhh0[20 + j];
    const float b1R  = 0.5f * (bih1[j] + bhh1[j]);
    const float b1Z  = 0.5f * (bih1[10 + j] + bhh1[10 + j]);
    const float b1XN = bih1[20 + j];
    const float b1HN = bhh1[20 + j];
    const float b2R  = 0.5f * (bih2[j] + bhh2[j]);
    const float b2Z  = 0.5f * (bih2[10 + j] + bhh2[10 + j]);
    const float b2XN = bih2[20 + j];
    const float b2HN = bhh2[20 + j];

    __syncthreads();

    const float* xe = x + (long)e * (T * IN);
    float xa0 = 0.f, xa1 = 0.f, xa2 = 0.f;
    if (act) { xa0 = xe[0]; xa1 = xe[1]; xa2 = xe[2]; }

    float myh0 = 0.f, myh1 = 0.f, myh2 = 0.f;

    for (int t = 0; t < T; ++t) {
        const int ob = t & 1;      // read buffer (h at t-1)
        const int nb = ob ^ 1;     // write buffer (h at t)

        // Prefetch next timestep's x.
        float xb0 = 0.f, xb1 = 0.f, xb2 = 0.f;
        if (act) {
            int tn = (t + 1 < T) ? (t + 1) : t;
            const float* p = xe + tn * IN;
            xb0 = p[0]; xb1 = p[1]; xb2 = p[2];
        }

        // ---- layer 0 (input width 3 scalar, h part packed) ----
        if (act) {
            u64 hv[5];
            load10p(&s_h[ob][0][eb][0], hv);
            u64 aR = 0ull, aZ = 0ull, aH = 0ull;
#pragma unroll
            for (int k = 0; k < 5; k++) {
                aR = fma2(w0h[0][k], hv[k], aR);
                aZ = fma2(w0h[1][k], hv[k], aZ);
                aH = fma2(w0h[2][k], hv[k], aH);
            }
            float xr  = fmaf(w0x[0][2], xa2, fmaf(w0x[0][1], xa1, fmaf(w0x[0][0], xa0, b0R)));
            float xz  = fmaf(w0x[1][2], xa2, fmaf(w0x[1][1], xa1, fmaf(w0x[1][0], xa0, b0Z)));
            float axn = fmaf(w0x[2][2], xa2, fmaf(w0x[2][1], xa1, fmaf(w0x[2][0], xa0, b0XN)));
            float r = sighalf(hsum2b(aR, xr));
            float z = sighalf(hsum2b(aZ, xz));
            float n = tanhapx(fmaf(r, hsum2b(aH, b0HN), axn));
            myh0 = n + z * (myh0 - n);
            s_h[nb][0][eb][j] = myh0;
        }
        __syncwarp();

        // ---- layer 1 ----
        if (act) {
            u64 iv[5], hv[5];
            load10p(&s_h[nb][0][eb][0], iv);
            load10p(&s_h[ob][1][eb][0], hv);
            myh1 = cell_reg(w1i, w1h, b1R, b1Z, b1XN, b1HN, iv, hv, myh1);
            s_h[nb][1][eb][j] = myh1;
        }
        __syncwarp();

        // ---- layer 2 ----
        if (act) {
            u64 iv[5], hv[5];
            load10p(&s_h[nb][1][eb][0], iv);
            load10p(&s_h[ob][2][eb][0], hv);
            myh2 = cell_reg(w2i, w2h, b2R, b2Z, b2XN, b2HN, iv, hv, myh2);
            s_h[nb][2][eb][j] = myh2;
        }
        __syncwarp();

        xa0 = xb0; xa1 = xb1; xa2 = xb2;
    }

    // Output head: out[e] = Wout . h2_final + bout (final h2 is in buffer T&1 = 0)
    if (act && j == 0) {
        const float* hp = &s_h[T & 1][2][eb][0];
        float acc = bout[0];
#pragma unroll
        for (int k = 0; k < 10; k++) acc = fmaf(Wout[k], hp[k], acc);
        out[e] = acc;
    }
}

} // namespace

extern "C" void kernel_launch(void* const* d_in, const int* in_sizes, int n_in,
                              void* d_out, int out_size) {
    const float* x    = (const float*)d_in[0];
    const float* Wih0 = (const float*)d_in[1];
    const float* Whh0 = (const float*)d_in[2];
    const float* bih0 = (const float*)d_in[3];
    const float* bhh0 = (const float*)d_in[4];
    const float* Wih1 = (const float*)d_in[5];
    const float* Whh1 = (const float*)d_in[6];
    const float* bih1 = (const float*)d_in[7];
    const float* bhh1 = (const float*)d_in[8];
    const float* Wih2 = (const float*)d_in[9];
    const float* Whh2 = (const float*)d_in[10];
    const float* bih2 = (const float*)d_in[11];
    const float* bhh2 = (const float*)d_in[12];
    const float* Wout = (const float*)d_in[13];
    const float* bout = (const float*)d_in[14];
    float* out = (float*)d_out;

    gru3_fused<<<NBLK, WARPS * 32>>>(x, Wih0, Whh0, bih0, bhh0,
                                     Wih1, Whh1, bih1, bhh1,
                                     Wih2, Whh2, bih2, bhh2,
                                     Wout, bout, out);
}

// round 6
// speedup vs baseline: 1.1615x; 1.1615x over previous
#include <cuda_runtime.h>

namespace {

using u64 = unsigned long long;

constexpr int B  = 4096;
constexpr int T  = 1000;
constexpr int IN = 3;

constexpr int WARPS = 4;            // 128 threads/block
constexpr int EPW   = 3;            // elements per warp (30 active lanes)
constexpr int EPB   = WARPS * EPW;  // 12
constexpr int NBLK  = (B + EPB - 1) / EPB;  // 342 -> 3 blocks/SM, single wave, 12 warps/SM
constexpr int RS    = 12;           // padded row stride (floats), 48B

// ---- packed f32x2 helpers ----
__device__ __forceinline__ u64 fma2(u64 a, u64 b, u64 c) {
    u64 d;
    asm("fma.rn.f32x2 %0, %1, %2, %3;" : "=l"(d) : "l"(a), "l"(b), "l"(c));
    return d;
}
__device__ __forceinline__ u64 pack2(float lo, float hi) {
    u64 d;
    asm("mov.b64 %0, {%1, %2};" : "=l"(d) : "f"(lo), "f"(hi));
    return d;
}
__device__ __forceinline__ float hsum2b(u64 v, float b) {
    float lo, hi;
    asm("mov.b64 {%0, %1}, %2;" : "=f"(lo), "=f"(hi) : "l"(v));
    return (lo + hi) + b;
}
__device__ __forceinline__ float tanhapx(float v) {
    float y;
    asm("tanh.approx.f32 %0, %1;" : "=f"(y) : "f"(v));
    return y;
}
// sigmoid(x) with a = x/2 (0.5 pre-folded into weights/biases)
__device__ __forceinline__ float sighalf(float a) {
    return fmaf(0.5f, tanhapx(a), 0.5f);
}

__device__ __forceinline__ void load10p(const float* __restrict__ p, u64* v) {
    ulonglong2 a = *reinterpret_cast<const ulonglong2*>(p);
    ulonglong2 b = *reinterpret_cast<const ulonglong2*>(p + 4);
    v[0] = a.x; v[1] = a.y; v[2] = b.x; v[3] = b.y;
    v[4] = *reinterpret_cast<const u64*>(p + 8);
}
__device__ __forceinline__ u64 dot5(const u64* __restrict__ w, const u64* __restrict__ v, u64 acc) {
#pragma unroll
    for (int k = 0; k < 5; k++) acc = fma2(w[k], v[k], acc);
    return acc;
}
// streamed dot: load a 10-row from smem and accumulate (limits transient regs)
__device__ __forceinline__ u64 dot5s(const float* __restrict__ wrow, const u64* __restrict__ v, u64 acc) {
    u64 w[5];
    load10p(wrow, w);
#pragma unroll
    for (int k = 0; k < 5; k++) acc = fma2(w[k], v[k], acc);
    return acc;
}

__global__ void __launch_bounds__(WARPS * 32, 3)
gru3_fused(const float* __restrict__ x,
           const float* __restrict__ Wih0, const float* __restrict__ Whh0,
           const float* __restrict__ bih0, const float* __restrict__ bhh0,
           const float* __restrict__ Wih1, const float* __restrict__ Whh1,
           const float* __restrict__ bih1, const float* __restrict__ bhh1,
           const float* __restrict__ Wih2, const float* __restrict__ Whh2,
           const float* __restrict__ bih2, const float* __restrict__ bhh2,
           const float* __restrict__ Wout, const float* __restrict__ bout,
           float* __restrict__ out)
{
    __shared__ __align__(16) float s_w2i[30 * RS], s_w2h[30 * RS];
    __shared__ __align__(16) float s_h[2][3][EPB][RS];

    const int tid  = threadIdx.x;
    const int lane = tid & 31;
    const int warp = tid >> 5;
    const int g    = lane / 10;
    const int j    = lane - g * 10;
    const int eb   = warp * EPW + g;
    const int e    = blockIdx.x * EPB + eb;
    const bool act = (lane < 30) && (e < B);

    // Stage layer-2 weights (r/z rows pre-scaled by 0.5 for folded sigmoid).
    for (int idx = tid; idx < 300; idx += WARPS * 32) {
        int r = idx / 10, c = idx - r * 10;
        float s = (r < 20) ? 0.5f : 1.0f;
        s_w2i[r * RS + c] = Wih2[idx] * s;
        s_w2h[r * RS + c] = Whh2[idx] * s;
    }
    for (int idx = tid; idx < 2 * 3 * EPB * RS; idx += WARPS * 32)
        (&s_h[0][0][0][0])[idx] = 0.0f;

    // ---- layer-0/1 weights in registers (r/z rows pre-scaled by 0.5) ----
    float w0x[3][3];
    u64 w0h[3][5], w1i[3][5], w1h[3][5];
#pragma unroll
    for (int gg = 0; gg < 3; gg++) {
        const int row = gg * 10 + j;
        const float s = (gg < 2) ? 0.5f : 1.0f;
#pragma unroll
        for (int k = 0; k < 3; k++) w0x[gg][k] = Wih0[row * 3 + k] * s;
#pragma unroll
        for (int k = 0; k < 5; k++) {
            w0h[gg][k] = pack2(Whh0[row * 10 + 2 * k] * s, Whh0[row * 10 + 2 * k + 1] * s);
            w1i[gg][k] = pack2(Wih1[row * 10 + 2 * k] * s, Wih1[row * 10 + 2 * k + 1] * s);
            w1h[gg][k] = pack2(Whh1[row * 10 + 2 * k] * s, Whh1[row * 10 + 2 * k + 1] * s);
        }
    }
    const float b0R  = 0.5f * (bih0[j] + bhh0[j]);
    const float b0Z  = 0.5f * (bih0[10 + j] + bhh0[10 + j]);
    const float b0XN = bih0[20 + j];
    const float b0HN = bhh0[20 + j];
    const float b1R  = 0.5f * (bih1[j] + bhh1[j]);
    const float b1Z  = 0.5f * (bih1[10 + j] + bhh1[10 + j]);
    const float b1XN = bih1[20 + j];
    const float b1HN = bhh1[20 + j];
    const float b2R  = 0.5f * (bih2[j] + bhh2[j]);
    const float b2Z  = 0.5f * (bih2[10 + j] + bhh2[10 + j]);
    const float b2XN = bih2[20 + j];
    const float b2HN = bhh2[20 + j];

    const float* w2i_r = s_w2i + j * RS;
    const float* w2i_z = s_w2i + (10 + j) * RS;
    const float* w2i_n = s_w2i + (20 + j) * RS;
    const float* w2h_r = s_w2h + j * RS;
    const float* w2h_z = s_w2h + (10 + j) * RS;
    const float* w2h_n = s_w2h + (20 + j) * RS;

    __syncthreads();

    const float* xe = x + (long)e * (T * IN);
    float myh0 = 0.f, myh1 = 0.f, myh2 = 0.f;

    // x pipeline: gx* = layer-0 x-gate dots for the CURRENT step; xc = raw x for NEXT step.
    float gxr = b0R, gxz = b0Z, gxn = b0XN;
    float xc0 = 0.f, xc1 = 0.f, xc2 = 0.f;
    if (act) {
        float a0 = xe[0], a1 = xe[1], a2 = xe[2];
        gxr = fmaf(w0x[0][2], a2, fmaf(w0x[0][1], a1, fmaf(w0x[0][0], a0, b0R)));
        gxz = fmaf(w0x[1][2], a2, fmaf(w0x[1][1], a1, fmaf(w0x[1][0], a0, b0Z)));
        gxn = fmaf(w0x[2][2], a2, fmaf(w0x[2][1], a1, fmaf(w0x[2][0], a0, b0XN)));
        xc0 = xe[IN]; xc1 = xe[IN + 1]; xc2 = xe[IN + 2];   // x[1]
    }

    auto step = [&](int t, int ob, int nb) {
        // ---- front: layer-0 finish + layer-0/1 recurrent dots (independent chains) ----
        if (act) {
            u64 h0p[5], h1p[5];
            load10p(&s_h[ob][0][eb][0], h0p);
            load10p(&s_h[ob][1][eb][0], h1p);
            u64 aR0 = 0, aZ0 = 0, aH0 = 0, aR1 = 0, aZ1 = 0, aH1 = 0;
#pragma unroll
            for (int k = 0; k < 5; k++) {
                aR0 = fma2(w0h[0][k], h0p[k], aR0);
                aR1 = fma2(w1h[0][k], h1p[k], aR1);
                aZ0 = fma2(w0h[1][k], h0p[k], aZ0);
                aZ1 = fma2(w1h[1][k], h1p[k], aZ1);
                aH0 = fma2(w0h[2][k], h0p[k], aH0);
                aH1 = fma2(w1h[2][k], h1p[k], aH1);
            }
            float r0 = sighalf(hsum2b(aR0, gxr));
            float z0 = sighalf(hsum2b(aZ0, gxz));
            float n0 = tanhapx(fmaf(r0, hsum2b(aH0, b0HN), gxn));
            myh0 = n0 + z0 * (myh0 - n0);
            s_h[nb][0][eb][j] = myh0;

            // stash layer-1 h-partials in persistent temps via lambda captures
            // (carried to mid-block below through these locals)
            __syncwarp();

            // ---- mid: layer-1 input dot + finish; layer-2 recurrent dot (streamed) ----
            u64 iv0[5], h2p[5];
            load10p(&s_h[nb][0][eb][0], iv0);
            load10p(&s_h[ob][2][eb][0], h2p);
            u64 aN1 = 0;
#pragma unroll
            for (int k = 0; k < 5; k++) {
                aR1 = fma2(w1i[0][k], iv0[k], aR1);
                aZ1 = fma2(w1i[1][k], iv0[k], aZ1);
                aN1 = fma2(w1i[2][k], iv0[k], aN1);
            }
            u64 aR2 = dot5s(w2h_r, h2p, 0);
            u64 aZ2 = dot5s(w2h_z, h2p, 0);
            u64 aH2 = dot5s(w2h_n, h2p, 0);
            float r1 = sighalf(hsum2b(aR1, b1R));
            float z1 = sighalf(hsum2b(aZ1, b1Z));
            float n1 = tanhapx(fmaf(r1, hsum2b(aH1, b1HN), hsum2b(aN1, b1XN)));
            myh1 = n1 + z1 * (myh1 - n1);
            s_h[nb][1][eb][j] = myh1;

            __syncwarp();

            // ---- tail: layer-2 input dot + finish; pipeline next x ----
            u64 iv1[5];
            load10p(&s_h[nb][1][eb][0], iv1);
            aR2 = dot5s(w2i_r, iv1, aR2);
            aZ2 = dot5s(w2i_z, iv1, aZ2);
            u64 aN2 = dot5s(w2i_n, iv1, 0);
            float r2 = sighalf(hsum2b(aR2, b2R));
            float z2 = sighalf(hsum2b(aZ2, b2Z));
            float n2 = tanhapx(fmaf(r2, hsum2b(aH2, b2HN), hsum2b(aN2, b2XN)));
            myh2 = n2 + z2 * (myh2 - n2);
            s_h[nb][2][eb][j] = myh2;

            // next-step x-gate dots from xc = x[t+1]; then prefetch x[t+2]
            gxr = fmaf(w0x[0][2], xc2, fmaf(w0x[0][1], xc1, fmaf(w0x[0][0], xc0, b0R)));
            gxz = fmaf(w0x[1][2], xc2, fmaf(w0x[1][1], xc1, fmaf(w0x[1][0], xc0, b0Z)));
            gxn = fmaf(w0x[2][2], xc2, fmaf(w0x[2][1], xc1, fmaf(w0x[2][0], xc0, b0XN)));
            int tn = (t + 2 < T) ? (t + 2) : (T - 1);
            const float* p = xe + tn * IN;
            xc0 = p[0]; xc1 = p[1]; xc2 = p[2];
        } else {
            __syncwarp();
            __syncwarp();
        }
        __syncwarp();
    };

#pragma unroll 1
    for (int t = 0; t < T; t += 2) {
        step(t, 0, 1);
        step(t + 1, 1, 0);
    }

    // Output head: final h2 is in buffer 0 after the last step.
    if (act && j == 0) {
        const float* hp = &s_h[0][2][eb][0];
        float acc = bout[0];
#pragma unroll
        for (int k = 0; k < 10; k++) acc = fmaf(Wout[k], hp[k], acc);
        out[e] = acc;
    }
}

} // namespace

extern "C" void kernel_launch(void* const* d_in, const int* in_sizes, int n_in,
                              void* d_out, int out_size) {
    const float* x    = (const float*)d_in[0];
    const float* Wih0 = (const float*)d_in[1];
    const float* Whh0 = (const float*)d_in[2];
    const float* bih0 = (const float*)d_in[3];
    const float* bhh0 = (const float*)d_in[4];
    const float* Wih1 = (const float*)d_in[5];
    const float* Whh1 = (const float*)d_in[6];
    const float* bih1 = (const float*)d_in[7];
    const float* bhh1 = (const float*)d_in[8];
    const float* Wih2 = (const float*)d_in[9];
    const float* Whh2 = (const float*)d_in[10];
    const float* bih2 = (const float*)d_in[11];
    const float* bhh2 = (const float*)d_in[12];
    const float* Wout = (const float*)d_in[13];
    const float* bout = (const float*)d_in[14];
    float* out = (float*)d_out;

    gru3_fused<<<NBLK, WARPS * 32>>>(x, Wih0, Whh0, bih0, bhh0,
                                     Wih1, Whh1, bih1, bhh1,
                                     Wih2, Whh2, bih2, bhh2,
                                     Wout, bout, out);
}

// round 7
// speedup vs baseline: 1.9603x; 1.6877x over previous
#include <cuda_runtime.h>

namespace {

using u64 = unsigned long long;

constexpr int B  = 4096;
constexpr int T  = 1000;

constexpr int WARPS = 4;            // 128 threads/block
constexpr int EPW   = 3;            // batch elements per warp
constexpr int EPB   = WARPS * EPW;  // 12
constexpr int NBLK  = (B + EPB - 1) / EPB;  // 342 -> 3 blocks/SM, single wave
constexpr int RS    = 12;           // padded row stride (floats), 48B

constexpr int HOFF = 3 * EPB * RS;  // float offset between s_h buffers
constexpr int XOFF = EPB * RS;      // float offset between s_x buffers

// ---- packed f32x2 helpers ----
__device__ __forceinline__ u64 fma2(u64 a, u64 b, u64 c) {
    u64 d;
    asm("fma.rn.f32x2 %0, %1, %2, %3;" : "=l"(d) : "l"(a), "l"(b), "l"(c));
    return d;
}
__device__ __forceinline__ u64 pack2(float lo, float hi) {
    u64 d;
    asm("mov.b64 %0, {%1, %2};" : "=l"(d) : "f"(lo), "f"(hi));
    return d;
}
__device__ __forceinline__ float hsum2b(u64 v, float b) {
    float lo, hi;
    asm("mov.b64 {%0, %1}, %2;" : "=f"(lo), "=f"(hi) : "l"(v));
    return (lo + hi) + b;
}
__device__ __forceinline__ float tanhapx(float v) {
    float y;
    asm("tanh.approx.f32 %0, %1;" : "=f"(y) : "f"(v));
    return y;
}
// sigmoid(x) with argument pre-scaled by 0.5 (folded into weights/biases)
__device__ __forceinline__ float sighalf(float a) {
    return fmaf(0.5f, tanhapx(a), 0.5f);
}

__device__ __forceinline__ void load10p(const float* __restrict__ p, u64* v) {
    ulonglong2 a = *reinterpret_cast<const ulonglong2*>(p);
    ulonglong2 b = *reinterpret_cast<const ulonglong2*>(p + 4);
    v[0] = a.x; v[1] = a.y; v[2] = b.x; v[3] = b.y;
    v[4] = *reinterpret_cast<const u64*>(p + 8);
}

__global__ void __launch_bounds__(WARPS * 32, 3)
gru3_pipe(const float* __restrict__ x,
          const float* __restrict__ Wih0, const float* __restrict__ Whh0,
          const float* __restrict__ bih0, const float* __restrict__ bhh0,
          const float* __restrict__ Wih1, const float* __restrict__ Whh1,
          const float* __restrict__ bih1, const float* __restrict__ bhh1,
          const float* __restrict__ Wih2, const float* __restrict__ Whh2,
          const float* __restrict__ bih2, const float* __restrict__ bhh2,
          const float* __restrict__ Wout, const float* __restrict__ bout,
          float* __restrict__ out)
{
    // [buf][layer][elem][unit] hidden-state exchange; [buf][elem][12] padded x rows
    __shared__ __align__(16) float s_h[2][3][EPB][RS];
    __shared__ __align__(16) float s_x[2][EPB][RS];

    const int tid  = threadIdx.x;
    const int lane = tid & 31;
    const int warp = tid >> 5;

    int  l = lane / 10;            // layer owned by this lane
    int  j = lane - l * 10;        // hidden unit owned by this lane
    const bool lane_ok = (lane < 30);
    if (!lane_ok) { l = 2; j = 9; }   // safe dummies; all their stores predicated off

    // zero both smem arrays
    for (int idx = tid; idx < 2 * HOFF; idx += WARPS * 32) (&s_h[0][0][0][0])[idx] = 0.0f;
    for (int idx = tid; idx < 2 * XOFF; idx += WARPS * 32) (&s_x[0][0][0])[idx]    = 0.0f;

    // ---- this lane's single layer: weights into registers (r/z rows pre-scaled 0.5) ----
    const float* Wi = (l == 0) ? Wih0 : (l == 1) ? Wih1 : Wih2;
    const float* Wh = (l == 0) ? Whh0 : (l == 1) ? Whh1 : Whh2;
    const float* bi = (l == 0) ? bih0 : (l == 1) ? bih1 : bih2;
    const float* bh = (l == 0) ? bhh0 : (l == 1) ? bhh1 : bhh2;
    const int in_w = (l == 0) ? 3 : 10;

    u64 wi[3][5], wh[3][5];
#pragma unroll
    for (int g = 0; g < 3; g++) {
        const int row = g * 10 + j;
        const float sc = (g < 2) ? 0.5f : 1.0f;
#pragma unroll
        for (int k = 0; k < 5; k++) {
            const int c0 = 2 * k, c1 = 2 * k + 1;
            float f0 = (c0 < in_w) ? Wi[row * in_w + c0] * sc : 0.0f;
            float f1 = (c1 < in_w) ? Wi[row * in_w + c1] * sc : 0.0f;
            wi[g][k] = pack2(f0, f1);
            wh[g][k] = pack2(Wh[row * 10 + c0] * sc, Wh[row * 10 + c1] * sc);
        }
    }
    const float bR  = 0.5f * (bi[j] + bh[j]);
    const float bZ  = 0.5f * (bi[10 + j] + bh[10 + j]);
    const float bXN = bi[20 + j];
    const float bHN = bh[20 + j];

    // element activity + row pointers (buffer 0; buffer 1 = +IOFF/+HOFF floats)
    bool ae[3];
    int  eg[3];
    const float* in0[3];
    const float* rec0[3];
    float*       wr0[3];
#pragma unroll
    for (int e = 0; e < 3; e++) {
        const int ebe = warp * EPW + e;
        eg[e] = blockIdx.x * EPB + ebe;
        ae[e] = lane_ok && (eg[e] < B);
        in0[e]  = (l == 0) ? &s_x[0][ebe][0] : &s_h[0][l - 1][ebe][0];
        rec0[e] = &s_h[0][l][ebe][0];
        wr0[e]  = &s_h[0][l][ebe][j];
    }
    const int IOFF = (l == 0) ? XOFF : HOFF;

    // x prefetch duty: layer-0 lanes j<9 each own (element pe, component pc)
    const bool pf  = (l == 0) && (j < 9);
    const int  pe  = j / 3, pc = j - pe * 3;
    const bool pfa = pf && lane_ok && ((blockIdx.x * EPB + warp * EPW + pe) < B);
    const float* xg = x + (size_t)(blockIdx.x * EPB + warp * EPW + pe) * (T * 3) + pc;
    float* sx0 = &s_x[0][warp * EPW + pe][pc];

    __syncthreads();

    // pipeline init: x[0] -> buf1 (read at s=0); xreg = x[1] (stored at s=0 into buf0)
    float xreg = 0.0f;
    if (pfa) { sx0[XOFF] = xg[0]; xreg = xg[3]; }
    __syncwarp();

    float myh[3] = {0.f, 0.f, 0.f};

    auto step = [&](int s, int bw, int br) {
        const int iro = br ? IOFF : 0;
        const int rro = br ? HOFF : 0;
        const int wo  = bw ? HOFF : 0;
#pragma unroll
        for (int e = 0; e < 3; e++) {
            u64 iv[5], hv[5];
            load10p(in0[e] + iro, iv);
            load10p(rec0[e] + rro, hv);
            u64 aR = 0, aZ = 0, aN = 0, aH = 0;
#pragma unroll
            for (int k = 0; k < 5; k++) {
                aR = fma2(wi[0][k], iv[k], aR);
                aZ = fma2(wi[1][k], iv[k], aZ);
                aN = fma2(wi[2][k], iv[k], aN);
            }
#pragma unroll
            for (int k = 0; k < 5; k++) {
                aR = fma2(wh[0][k], hv[k], aR);
                aZ = fma2(wh[1][k], hv[k], aZ);
                aH = fma2(wh[2][k], hv[k], aH);
            }
            const float r = sighalf(hsum2b(aR, bR));
            const float z = sighalf(hsum2b(aZ, bZ));
            const float n = tanhapx(fmaf(r, hsum2b(aH, bHN), hsum2b(aN, bXN)));
            const float hn = n + z * (myh[e] - n);
            // pipeline validity: layer l computes timestep s-l, valid when 0 <= s-l < T
            if (ae[e] && (s >= l) && (s <= (T - 1) + l)) {
                myh[e] = hn;
                wr0[e][wo] = hn;
            }
        }
        // x staging: store x[s+1] into write buffer; prefetch x[s+2]
        if (pfa) {
            sx0[bw ? XOFF : 0] = xreg;
            int idx = s + 2; if (idx > T - 1) idx = T - 1;
            xreg = xg[idx * 3];
        }
        __syncwarp();
    };

#pragma unroll 1
    for (int s = 0; s < T + 2; s += 2) {   // T+2 = 1002 steps, even
        step(s, 0, 1);
        step(s + 1, 1, 0);
    }

    // Output head. Final h2[T-1] was stored at step s=T+1 (buf 1) into s_h[1][2][ebe].
    if (l == 2 && j < 3) {
        const int e = j;
        if (ae[e]) {
            const float* hp = rec0[e] + HOFF;   // s_h[1][2][ebe]
            float acc = bout[0];
#pragma unroll
            for (int k = 0; k < 10; k++) acc = fmaf(Wout[k], hp[k], acc);
            out[eg[e]] = acc;
        }
    }
}

} // namespace

extern "C" void kernel_launch(void* const* d_in, const int* in_sizes, int n_in,
                              void* d_out, int out_size) {
    const float* x    = (const float*)d_in[0];
    const float* Wih0 = (const float*)d_in[1];
    const float* Whh0 = (const float*)d_in[2];
    const float* bih0 = (const float*)d_in[3];
    const float* bhh0 = (const float*)d_in[4];
    const float* Wih1 = (const float*)d_in[5];
    const float* Whh1 = (const float*)d_in[6];
    const float* bih1 = (const float*)d_in[7];
    const float* bhh1 = (const float*)d_in[8];
    const float* Wih2 = (const float*)d_in[9];
    const float* Whh2 = (const float*)d_in[10];
    const float* bih2 = (const float*)d_in[11];
    const float* bhh2 = (const float*)d_in[12];
    const float* Wout = (const float*)d_in[13];
    const float* bout = (const float*)d_in[14];
    float* out = (float*)d_out;

    gru3_pipe<<<NBLK, WARPS * 32>>>(x, Wih0, Whh0, bih0, bhh0,
                                    Wih1, Whh1, bih1, bhh1,
                                    Wih2, Whh2, bih2, bhh2,
                                    Wout, bout, out);
}

// round 8
// speedup vs baseline: 2.1217x; 1.0823x over previous
#include <cuda_runtime.h>

namespace {

using u64 = unsigned long long;

constexpr int B  = 4096;
constexpr int T  = 1000;

constexpr int WARPS = 4;             // 128 threads/block
constexpr int EPW   = 4;             // batch elements per warp
constexpr int EPB   = WARPS * EPW;   // 16
constexpr int NBLK  = B / EPB;       // 256 blocks -> <=2 blocks/SM, single wave, 8 warps/SM
constexpr int RS    = 12;            // padded row stride (floats)
constexpr int EPP   = EPB + EPW;     // 20 rows: 16 real + 4 scratch for dummy lanes

constexpr int HOFF = 3 * EPP * RS;   // float stride between s_h ping-pong buffers
constexpr int XOFF = EPP * RS;       // float stride between s_x ping-pong buffers

// ---- packed f32x2 helpers ----
__device__ __forceinline__ u64 fma2(u64 a, u64 b, u64 c) {
    u64 d;
    asm("fma.rn.f32x2 %0, %1, %2, %3;" : "=l"(d) : "l"(a), "l"(b), "l"(c));
    return d;
}
__device__ __forceinline__ u64 pack2(float lo, float hi) {
    u64 d;
    asm("mov.b64 %0, {%1, %2};" : "=l"(d) : "f"(lo), "f"(hi));
    return d;
}
__device__ __forceinline__ float hsum2(u64 v) {
    float lo, hi;
    asm("mov.b64 {%0, %1}, %2;" : "=f"(lo), "=f"(hi) : "l"(v));
    return lo + hi;
}
__device__ __forceinline__ float tanhapx(float v) {
    float y;
    asm("tanh.approx.f32 %0, %1;" : "=f"(y) : "f"(v));
    return y;
}
// sigmoid(x) with argument pre-scaled by 0.5 (folded into weights/biases)
__device__ __forceinline__ float sighalf(float a) {
    return fmaf(0.5f, tanhapx(a), 0.5f);
}

__device__ __forceinline__ void load10p(const float* __restrict__ p, u64* v) {
    ulonglong2 a = *reinterpret_cast<const ulonglong2*>(p);
    ulonglong2 b = *reinterpret_cast<const ulonglong2*>(p + 4);
    v[0] = a.x; v[1] = a.y; v[2] = b.x; v[3] = b.y;
    v[4] = *reinterpret_cast<const u64*>(p + 8);
}

__global__ void __launch_bounds__(WARPS * 32, 2)
gru3_pipe4(const float* __restrict__ x,
           const float* __restrict__ Wih0, const float* __restrict__ Whh0,
           const float* __restrict__ bih0, const float* __restrict__ bhh0,
           const float* __restrict__ Wih1, const float* __restrict__ Whh1,
           const float* __restrict__ bih1, const float* __restrict__ bhh1,
           const float* __restrict__ Wih2, const float* __restrict__ Whh2,
           const float* __restrict__ bih2, const float* __restrict__ bhh2,
           const float* __restrict__ Wout, const float* __restrict__ bout,
           float* __restrict__ out)
{
    __shared__ __align__(16) float s_h[2][3][EPP][RS];
    __shared__ __align__(16) float s_x[2][EPP][RS];

    const int tid  = threadIdx.x;
    const int lane = tid & 31;
    const int warp = tid >> 5;

    int  l = lane / 10;            // layer owned by this lane
    int  j = lane - l * 10;        // hidden unit owned by this lane
    const bool lane_ok = (lane < 30);
    if (!lane_ok) { l = 2; j = 9; }   // dummies: real weights, scratch rows

    for (int idx = tid; idx < 2 * HOFF; idx += WARPS * 32) (&s_h[0][0][0][0])[idx] = 0.0f;
    for (int idx = tid; idx < 2 * XOFF; idx += WARPS * 32) (&s_x[0][0][0])[idx]    = 0.0f;

    // ---- this lane's layer weights -> registers (r/z rows pre-scaled by 0.5) ----
    const float* Wi = (l == 0) ? Wih0 : (l == 1) ? Wih1 : Wih2;
    const float* Wh = (l == 0) ? Whh0 : (l == 1) ? Whh1 : Whh2;
    const float* bi = (l == 0) ? bih0 : (l == 1) ? bih1 : bih2;
    const float* bh = (l == 0) ? bhh0 : (l == 1) ? bhh1 : bhh2;
    const int in_w = (l == 0) ? 3 : 10;

    u64 wi[3][5], wh[3][5];
#pragma unroll
    for (int g = 0; g < 3; g++) {
        const int row = g * 10 + j;
        const float sc = (g < 2) ? 0.5f : 1.0f;
#pragma unroll
        for (int k = 0; k < 5; k++) {
            const int c0 = 2 * k, c1 = 2 * k + 1;
            float f0 = (c0 < in_w) ? Wi[row * in_w + c0] * sc : 0.0f;
            float f1 = (c1 < in_w) ? Wi[row * in_w + c1] * sc : 0.0f;
            wi[g][k] = pack2(f0, f1);
            wh[g][k] = pack2(Wh[row * 10 + c0] * sc, Wh[row * 10 + c1] * sc);
        }
    }
    // Bias packs: accumulator initializers (bias in lo half, 0 in hi).
    const u64 bRp = pack2(0.5f * (bi[j] + bh[j]), 0.f);
    const u64 bZp = pack2(0.5f * (bi[10 + j] + bh[10 + j]), 0.f);
    const u64 bNp = pack2(bi[20 + j], 0.f);
    const u64 bHp = pack2(bh[20 + j], 0.f);

    // Base row (element e uses base + e*RS; dummies get scratch rows 16..19).
    const int ebe0 = lane_ok ? warp * EPW : EPB;
    const float* in_base  = (l == 0) ? &s_x[0][ebe0][0] : &s_h[0][l - 1][ebe0][0];
    const float* rec_base = &s_h[0][l][ebe0][0];
    float*       wr_base  = &s_h[0][l][ebe0][j];
    const int IOFF = (l == 0) ? XOFF : HOFF;

    // x prefetch duty: lanes 0..11 own (element pe, component pc) of their warp.
    const bool pf = (lane < 12);
    const int  pe = lane / 3, pc = lane - pe * 3;
    const float* xg = x + (size_t)(blockIdx.x * EPB + warp * EPW + pe) * (T * 3) + pc;
    float* sxp = &s_x[0][warp * EPW + pe][pc];

    __syncthreads();

    // pipeline init: x[0] -> buf1 (read at s=0); xreg = x[1] (stored during s=0).
    float xreg = 0.0f;
    if (pf) { sxp[XOFF] = xg[0]; xreg = xg[3]; }
    __syncwarp();

    float myh[EPW] = {0.f, 0.f, 0.f, 0.f};

    auto step = [&](int s, int bw, bool edge) {
        const int br  = bw ^ 1;
        const int iro = br ? IOFF : 0;
        const int rro = br ? HOFF : 0;
        const int wo  = bw ? HOFF : 0;
#pragma unroll
        for (int e = 0; e < EPW; e++) {
            u64 iv[5], hv[5];
            load10p(in_base  + iro + e * RS, iv);
            load10p(rec_base + rro + e * RS, hv);
            u64 aR = bRp, aZ = bZp, aN = bNp, aH = bHp;
#pragma unroll
            for (int k = 0; k < 5; k++) {
                aR = fma2(wi[0][k], iv[k], aR);
                aZ = fma2(wi[1][k], iv[k], aZ);
                aN = fma2(wi[2][k], iv[k], aN);
            }
#pragma unroll
            for (int k = 0; k < 5; k++) {
                aR = fma2(wh[0][k], hv[k], aR);
                aZ = fma2(wh[1][k], hv[k], aZ);
                aH = fma2(wh[2][k], hv[k], aH);
            }
            const float r  = sighalf(hsum2(aR));
            const float z  = sighalf(hsum2(aZ));
            const float n  = tanhapx(fmaf(r, hsum2(aH), hsum2(aN)));
            const float hn = n + z * (myh[e] - n);
            // layer l computes timestep s-l; valid iff 0 <= s-l < T
            if (!edge || ((unsigned)(s - l) < (unsigned)T)) {
                myh[e] = hn;
                wr_base[wo + e * RS] = hn;
            }
        }
        if (pf) {
            sxp[bw ? XOFF : 0] = xreg;               // stage x[s+1]
            int idx = s + 2; if (idx > T - 1) idx = T - 1;
            xreg = xg[idx * 3];                      // prefetch x[s+2]
        }
        __syncwarp();
    };

    step(0, 0, true);
    step(1, 1, true);
#pragma unroll 1
    for (int s = 2; s < T; s += 2) {      // s = 2 .. 999, unconditional body
        step(s,     0, false);
        step(s + 1, 1, false);
    }
    step(T,     0, true);                 // s = 1000
    step(T + 1, 1, true);                 // s = 1001 -> final h2 in buffer 1

    // Output head: lanes (l==2, j<EPW) each dot one element's final h2 row.
    if (l == 2 && j < EPW && lane_ok) {
        const float* hp = rec_base + HOFF + j * RS;   // s_h[1][2][ebe0+j]
        float acc = bout[0];
#pragma unroll
        for (int k = 0; k < 10; k++) acc = fmaf(Wout[k], hp[k], acc);
        out[blockIdx.x * EPB + ebe0 + j] = acc;
    }
}

} // namespace

extern "C" void kernel_launch(void* const* d_in, const int* in_sizes, int n_in,
                              void* d_out, int out_size) {
    const float* x    = (const float*)d_in[0];
    const float* Wih0 = (const float*)d_in[1];
    const float* Whh0 = (const float*)d_in[2];
    const float* bih0 = (const float*)d_in[3];
    const float* bhh0 = (const float*)d_in[4];
    const float* Wih1 = (const float*)d_in[5];
    const float* Whh1 = (const float*)d_in[6];
    const float* bih1 = (const float*)d_in[7];
    const float* bhh1 = (const float*)d_in[8];
    const float* Wih2 = (const float*)d_in[9];
    const float* Whh2 = (const float*)d_in[10];
    const float* bih2 = (const float*)d_in[11];
    const float* bhh2 = (const float*)d_in[12];
    const float* Wout = (const float*)d_in[13];
    const float* bout = (const float*)d_in[14];
    float* out = (float*)d_out;

    gru3_pipe4<<<NBLK, WARPS * 32>>>(x, Wih0, Whh0, bih0, bhh0,
                                     Wih1, Whh1, bih1, bhh1,
                                     Wih2, Whh2, bih2, bhh2,
                                     Wout, bout, out);
}

// round 9
// speedup vs baseline: 2.2276x; 1.0499x over previous
#include <cuda_runtime.h>

namespace {

using u64 = unsigned long long;

constexpr int B  = 4096;
constexpr int T  = 1000;

constexpr int WARPS = 4;             // 128 threads/block
constexpr int EPW   = 2;             // batch elements per warp
constexpr int EPB   = WARPS * EPW;   // 8
constexpr int NBLK  = B / EPB;       // 512 blocks -> <=4 blocks/SM, single wave, 4 warps/SMSP
constexpr int RS    = 12;            // padded row stride (floats)
constexpr int EPP   = EPB + EPW;     // 10 rows: 8 real + 2 scratch for dummy lanes

constexpr int HOFF = 3 * EPP * RS;   // float stride between s_h ping-pong buffers
constexpr int XOFF = EPP * RS;       // float stride between s_x ping-pong buffers

// ---- packed f32x2 helpers ----
__device__ __forceinline__ u64 fma2(u64 a, u64 b, u64 c) {
    u64 d;
    asm("fma.rn.f32x2 %0, %1, %2, %3;" : "=l"(d) : "l"(a), "l"(b), "l"(c));
    return d;
}
__device__ __forceinline__ u64 pack2(float lo, float hi) {
    u64 d;
    asm("mov.b64 %0, {%1, %2};" : "=l"(d) : "f"(lo), "f"(hi));
    return d;
}
__device__ __forceinline__ float hsum2(u64 v) {
    float lo, hi;
    asm("mov.b64 {%0, %1}, %2;" : "=f"(lo), "=f"(hi) : "l"(v));
    return lo + hi;
}
__device__ __forceinline__ float tanhapx(float v) {
    float y;
    asm("tanh.approx.f32 %0, %1;" : "=f"(y) : "f"(v));
    return y;
}
// sigmoid(x) with argument pre-scaled by 0.5 (folded into weights/biases)
__device__ __forceinline__ float sighalf(float a) {
    return fmaf(0.5f, tanhapx(a), 0.5f);
}

__device__ __forceinline__ void load10p(const float* __restrict__ p, u64* v) {
    ulonglong2 a = *reinterpret_cast<const ulonglong2*>(p);
    ulonglong2 b = *reinterpret_cast<const ulonglong2*>(p + 4);
    v[0] = a.x; v[1] = a.y; v[2] = b.x; v[3] = b.y;
    v[4] = *reinterpret_cast<const u64*>(p + 8);
}

__global__ void __launch_bounds__(WARPS * 32, 4)
gru3_pipe2(const float* __restrict__ x,
           const float* __restrict__ Wih0, const float* __restrict__ Whh0,
           const float* __restrict__ bih0, const float* __restrict__ bhh0,
           const float* __restrict__ Wih1, const float* __restrict__ Whh1,
           const float* __restrict__ bih1, const float* __restrict__ bhh1,
           const float* __restrict__ Wih2, const float* __restrict__ Whh2,
           const float* __restrict__ bih2, const float* __restrict__ bhh2,
           const float* __restrict__ Wout, const float* __restrict__ bout,
           float* __restrict__ out)
{
    __shared__ __align__(16) float s_h[2][3][EPP][RS];
    __shared__ __align__(16) float s_x[2][EPP][RS];

    const int tid  = threadIdx.x;
    const int lane = tid & 31;
    const int warp = tid >> 5;

    int  l = lane / 10;            // layer owned by this lane
    int  j = lane - l * 10;        // hidden unit owned by this lane
    const bool lane_ok = (lane < 30);
    if (!lane_ok) { l = 2; j = 9; }   // dummies: real weights, scratch rows

    for (int idx = tid; idx < 2 * HOFF; idx += WARPS * 32) (&s_h[0][0][0][0])[idx] = 0.0f;
    for (int idx = tid; idx < 2 * XOFF; idx += WARPS * 32) (&s_x[0][0][0])[idx]    = 0.0f;

    // ---- this lane's layer weights -> registers (r/z rows pre-scaled by 0.5) ----
    const float* Wi = (l == 0) ? Wih0 : (l == 1) ? Wih1 : Wih2;
    const float* Wh = (l == 0) ? Whh0 : (l == 1) ? Whh1 : Whh2;
    const float* bi = (l == 0) ? bih0 : (l == 1) ? bih1 : bih2;
    const float* bh = (l == 0) ? bhh0 : (l == 1) ? bhh1 : bhh2;
    const int in_w = (l == 0) ? 3 : 10;

    u64 wi[3][5], wh[3][5];
#pragma unroll
    for (int g = 0; g < 3; g++) {
        const int row = g * 10 + j;
        const float sc = (g < 2) ? 0.5f : 1.0f;
#pragma unroll
        for (int k = 0; k < 5; k++) {
            const int c0 = 2 * k, c1 = 2 * k + 1;
            float f0 = (c0 < in_w) ? Wi[row * in_w + c0] * sc : 0.0f;
            float f1 = (c1 < in_w) ? Wi[row * in_w + c1] * sc : 0.0f;
            wi[g][k] = pack2(f0, f1);
            wh[g][k] = pack2(Wh[row * 10 + c0] * sc, Wh[row * 10 + c1] * sc);
        }
    }
    // Bias packs: accumulator initializers (bias in lo half, 0 in hi).
    const u64 bRp = pack2(0.5f * (bi[j] + bh[j]), 0.f);
    const u64 bZp = pack2(0.5f * (bi[10 + j] + bh[10 + j]), 0.f);
    const u64 bNp = pack2(bi[20 + j], 0.f);
    const u64 bHp = pack2(bh[20 + j], 0.f);

    // Base row (element e uses base + e*RS; dummies use scratch rows EPB..EPP-1).
    const int ebe0 = lane_ok ? warp * EPW : EPB;
    const float* in_base  = (l == 0) ? &s_x[0][ebe0][0] : &s_h[0][l - 1][ebe0][0];
    const float* rec_base = &s_h[0][l][ebe0][0];
    float*       wr_base  = &s_h[0][l][ebe0][j];
    const int IOFF = (l == 0) ? XOFF : HOFF;

    // x prefetch duty: lanes 0..(EPW*3-1) own (element pe, component pc).
    const bool pf = (lane < EPW * 3);
    const int  pe = lane / 3, pc = lane - pe * 3;
    const float* xg = x + (size_t)(blockIdx.x * EPB + warp * EPW + pe) * (T * 3) + pc;
    float* sxp = &s_x[0][warp * EPW + pe][pc];

    __syncthreads();

    // pipeline init: x[0] -> buf1 (read at s=0); xreg = x[1] (stored during s=0).
    float xreg = 0.0f;
    if (pf) { sxp[XOFF] = xg[0]; xreg = xg[3]; }
    __syncwarp();

    float myh[EPW] = {0.f, 0.f};

    auto step = [&](int s, int bw, bool edge) {
        const int br  = bw ^ 1;
        const int iro = br ? IOFF : 0;
        const int rro = br ? HOFF : 0;
        const int wo  = bw ? HOFF : 0;
#pragma unroll
        for (int e = 0; e < EPW; e++) {
            u64 iv[5], hv[5];
            load10p(in_base  + iro + e * RS, iv);
            load10p(rec_base + rro + e * RS, hv);
            u64 aR = bRp, aZ = bZp, aN = bNp, aH = bHp;
#pragma unroll
            for (int k = 0; k < 5; k++) {
                aR = fma2(wi[0][k], iv[k], aR);
                aZ = fma2(wi[1][k], iv[k], aZ);
                aN = fma2(wi[2][k], iv[k], aN);
            }
#pragma unroll
            for (int k = 0; k < 5; k++) {
                aR = fma2(wh[0][k], hv[k], aR);
                aZ = fma2(wh[1][k], hv[k], aZ);
                aH = fma2(wh[2][k], hv[k], aH);
            }
            const float r  = sighalf(hsum2(aR));
            const float z  = sighalf(hsum2(aZ));
            const float n  = tanhapx(fmaf(r, hsum2(aH), hsum2(aN)));
            const float hn = n + z * (myh[e] - n);
            // layer l computes timestep s-l; valid iff 0 <= s-l < T
            if (!edge || ((unsigned)(s - l) < (unsigned)T)) {
                myh[e] = hn;
                wr_base[wo + e * RS] = hn;
            }
        }
        if (pf) {
            sxp[bw ? XOFF : 0] = xreg;               // stage x[s+1]
            int idx = s + 2; if (idx > T - 1) idx = T - 1;
            xreg = xg[idx * 3];                      // prefetch x[s+2]
        }
        __syncwarp();
    };

    step(0, 0, true);
    step(1, 1, true);
#pragma unroll 1
    for (int s = 2; s < T; s += 2) {      // s = 2 .. 999, unconditional body
        step(s,     0, false);
        step(s + 1, 1, false);
    }
    step(T,     0, true);                 // s = 1000
    step(T + 1, 1, true);                 // s = 1001 -> final h2 in buffer 1

    // Output head: lanes (l==2, j<EPW) each dot one element's final h2 row.
    if (l == 2 && j < EPW && lane_ok) {
        const float* hp = rec_base + HOFF + j * RS;   // s_h[1][2][ebe0+j]
        float acc = bout[0];
#pragma unroll
        for (int k = 0; k < 10; k++) acc = fmaf(Wout[k], hp[k], acc);
        out[blockIdx.x * EPB + ebe0 + j] = acc;
    }
}

} // namespace

extern "C" void kernel_launch(void* const* d_in, const int* in_sizes, int n_in,
                              void* d_out, int out_size) {
    const float* x    = (const float*)d_in[0];
    const float* Wih0 = (const float*)d_in[1];
    const float* Whh0 = (const float*)d_in[2];
    const float* bih0 = (const float*)d_in[3];
    const float* bhh0 = (const float*)d_in[4];
    const float* Wih1 = (const float*)d_in[5];
    const float* Whh1 = (const float*)d_in[6];
    const float* bih1 = (const float*)d_in[7];
    const float* bhh1 = (const float*)d_in[8];
    const float* Wih2 = (const float*)d_in[9];
    const float* Whh2 = (const float*)d_in[10];
    const float* bih2 = (const float*)d_in[11];
    const float* bhh2 = (const float*)d_in[12];
    const float* Wout = (const float*)d_in[13];
    const float* bout = (const float*)d_in[14];
    float* out = (float*)d_out;

    gru3_pipe2<<<NBLK, WARPS * 32>>>(x, Wih0, Whh0, bih0, bhh0,
                                     Wih1, Whh1, bih1, bhh1,
                                     Wih2, Whh2, bih2, bhh2,
                                     Wout, bout, out);
}